// round 1
// baseline (speedup 1.0000x reference)
#include <cuda_runtime.h>

// ---------------------------------------------------------------------------
// SlidingWindowTransformer: B=4,S=512,D=256,W=32,L=4,H=8,DH=32,DFF=1024,NOUT=32
// Round 0: fp32-exact, GEMM-centric multi-kernel baseline.
// ---------------------------------------------------------------------------

namespace {
constexpr int Dm   = 256;
constexpr int Wn   = 32;
constexpr int DFF  = 1024;
constexpr int NWIN = 2048;            // B*S
constexpr int NTOK = NWIN * Wn;       // 65536
constexpr float EPS   = 1e-5f;
constexpr float SCALE = 0.17677669529663687f;  // 32^-0.5
}

// Scratch (static device allocations are allowed; cudaMalloc is not).
__device__ float g_x  [(size_t)NTOK * Dm];    // current activations (64 MB)
__device__ float g_big[(size_t)NTOK * DFF];   // qkv (N=768) / ffn hidden (N=1024)
__device__ float g_att[(size_t)NTOK * Dm];    // attention concat output
__device__ float g_tmp[(size_t)NTOK * Dm];    // gemm outputs (o-proj / ffn2)

// ---------------------------------------------------------------------------
// Gather: g_x[n][w][:] = X[b][clip(s-w,0)][:] + pos_embed[w][:]
// ---------------------------------------------------------------------------
__global__ void gather_kernel(const float* __restrict__ X,
                              const float* __restrict__ pos) {
    int idx = blockIdx.x * 256 + threadIdx.x;   // float4 index over NTOK*64
    int d4 = idx & 63;
    int w  = (idx >> 6) & 31;
    int n  = idx >> 11;
    int s  = n & 511;
    int b  = n >> 9;
    int src = s - w; if (src < 0) src = 0;
    float4 xv = reinterpret_cast<const float4*>(X)[(size_t)(b * 512 + src) * 64 + d4];
    float4 pv = reinterpret_cast<const float4*>(pos)[(size_t)w * 64 + d4];
    float4 o  = make_float4(xv.x + pv.x, xv.y + pv.y, xv.z + pv.z, xv.w + pv.w);
    reinterpret_cast<float4*>(g_x)[idx] = o;
}

// ---------------------------------------------------------------------------
// SGEMM (NT): C[M,N] = A[M,K] @ Bw[N,K]^T + bias[N]  (optional ReLU)
// 128x128 block tile, BK=16, 8x8 microtile, 256 threads. All dims divide tiles.
// ---------------------------------------------------------------------------
template <bool RELU>
__global__ void __launch_bounds__(256, 2) sgemm_nt(
    const float* __restrict__ A, const float* __restrict__ Bw,
    const float* __restrict__ bias, float* __restrict__ C,
    int M, int N, int K)
{
    __shared__ float As[16][128];
    __shared__ float Bs[16][128];

    const int tid = threadIdx.x;
    const int bm  = blockIdx.y * 128;
    const int bn  = blockIdx.x * 128;
    const int tx  = tid & 15;
    const int ty  = tid >> 4;

    float acc[8][8];
#pragma unroll
    for (int i = 0; i < 8; i++)
#pragma unroll
        for (int j = 0; j < 8; j++) acc[i][j] = 0.f;

    for (int k0 = 0; k0 < K; k0 += 16) {
#pragma unroll
        for (int i = 0; i < 2; i++) {
            int f   = tid + i * 256;        // float4 id in [0,512)
            int row = f >> 2;
            int kg  = (f & 3) * 4;
            float4 va = *reinterpret_cast<const float4*>(
                &A[(size_t)(bm + row) * K + k0 + kg]);
            As[kg + 0][row] = va.x; As[kg + 1][row] = va.y;
            As[kg + 2][row] = va.z; As[kg + 3][row] = va.w;
            float4 vb = *reinterpret_cast<const float4*>(
                &Bw[(size_t)(bn + row) * K + k0 + kg]);
            Bs[kg + 0][row] = vb.x; Bs[kg + 1][row] = vb.y;
            Bs[kg + 2][row] = vb.z; Bs[kg + 3][row] = vb.w;
        }
        __syncthreads();
#pragma unroll
        for (int kk = 0; kk < 16; kk++) {
            float a[8], b[8];
            *reinterpret_cast<float4*>(&a[0]) =
                *reinterpret_cast<const float4*>(&As[kk][ty * 8]);
            *reinterpret_cast<float4*>(&a[4]) =
                *reinterpret_cast<const float4*>(&As[kk][ty * 8 + 4]);
            *reinterpret_cast<float4*>(&b[0]) =
                *reinterpret_cast<const float4*>(&Bs[kk][tx * 8]);
            *reinterpret_cast<float4*>(&b[4]) =
                *reinterpret_cast<const float4*>(&Bs[kk][tx * 8 + 4]);
#pragma unroll
            for (int i = 0; i < 8; i++)
#pragma unroll
                for (int j = 0; j < 8; j++)
                    acc[i][j] = fmaf(a[i], b[j], acc[i][j]);
        }
        __syncthreads();
    }

#pragma unroll
    for (int i = 0; i < 8; i++) {
        int m = bm + ty * 8 + i;
#pragma unroll
        for (int jg = 0; jg < 2; jg++) {
            int n = bn + tx * 8 + jg * 4;
            float4 bv = *reinterpret_cast<const float4*>(&bias[n]);
            float4 o;
            o.x = acc[i][jg * 4 + 0] + bv.x;
            o.y = acc[i][jg * 4 + 1] + bv.y;
            o.z = acc[i][jg * 4 + 2] + bv.z;
            o.w = acc[i][jg * 4 + 3] + bv.w;
            if (RELU) {
                o.x = fmaxf(o.x, 0.f); o.y = fmaxf(o.y, 0.f);
                o.z = fmaxf(o.z, 0.f); o.w = fmaxf(o.w, 0.f);
            }
            *reinterpret_cast<float4*>(&C[(size_t)m * N + n]) = o;
        }
    }
}

// ---------------------------------------------------------------------------
// Attention: one block per (window, head). qkv layout: [token][768],
// q = cols [h*32, h*32+32), k at +256, v at +512. Writes concat to g_att.
// ---------------------------------------------------------------------------
__global__ void attn_kernel(const float* __restrict__ qkv) {
    int n = blockIdx.x >> 3;
    int h = blockIdx.x & 7;
    int tid = threadIdx.x;   // 128 threads
    __shared__ float qs[32][32];
    __shared__ float ks[32][33];
    __shared__ float vs[32][33];
    __shared__ float ps[32][33];

    int base = n * 32;
    int hc   = h * 32;
    for (int idx = tid; idx < 1024; idx += 128) {
        int i = idx >> 5, d = idx & 31;
        const float* row = qkv + (size_t)(base + i) * 768;
        qs[i][d] = row[hc + d];
        ks[i][d] = row[256 + hc + d];
        vs[i][d] = row[512 + hc + d];
    }
    __syncthreads();

    for (int idx = tid; idx < 1024; idx += 128) {
        int i = idx >> 5, j = idx & 31;
        float s = 0.f;
#pragma unroll
        for (int d = 0; d < 32; d++) s = fmaf(qs[i][d], ks[j][d], s);
        ps[i][j] = s * SCALE;
    }
    __syncthreads();

    if (tid < 32) {
        float mx = -1e30f;
#pragma unroll
        for (int j = 0; j < 32; j++) mx = fmaxf(mx, ps[tid][j]);
        float sum = 0.f;
#pragma unroll
        for (int j = 0; j < 32; j++) {
            float e = __expf(ps[tid][j] - mx);
            ps[tid][j] = e;
            sum += e;
        }
        float inv = 1.f / sum;
#pragma unroll
        for (int j = 0; j < 32; j++) ps[tid][j] *= inv;
    }
    __syncthreads();

    for (int idx = tid; idx < 1024; idx += 128) {
        int i = idx >> 5, d = idx & 31;
        float s = 0.f;
#pragma unroll
        for (int j = 0; j < 32; j++) s = fmaf(ps[i][j], vs[j][d], s);
        g_att[(size_t)(base + i) * 256 + hc + d] = s;
    }
}

// ---------------------------------------------------------------------------
// Residual add + LayerNorm, in-place on g_x. Warp per token (256 elems).
// ---------------------------------------------------------------------------
__global__ void add_ln_kernel(const float* __restrict__ y,
                              const float* __restrict__ g,
                              const float* __restrict__ b) {
    int warp  = threadIdx.x >> 5;
    int lane  = threadIdx.x & 31;
    int token = blockIdx.x * 8 + warp;
    float* xr = g_x + (size_t)token * 256;
    const float* yr = y + (size_t)token * 256;

    float v[8];
    float s = 0.f;
#pragma unroll
    for (int j = 0; j < 8; j++) {
        int c = lane + j * 32;
        v[j] = xr[c] + yr[c];
        s += v[j];
    }
#pragma unroll
    for (int o = 16; o > 0; o >>= 1) s += __shfl_xor_sync(0xffffffffu, s, o);
    float mu = s * (1.f / 256.f);
    float s2 = 0.f;
#pragma unroll
    for (int j = 0; j < 8; j++) { float d = v[j] - mu; s2 += d * d; }
#pragma unroll
    for (int o = 16; o > 0; o >>= 1) s2 += __shfl_xor_sync(0xffffffffu, s2, o);
    float rstd = rsqrtf(s2 * (1.f / 256.f) + EPS);
#pragma unroll
    for (int j = 0; j < 8; j++) {
        int c = lane + j * 32;
        xr[c] = (v[j] - mu) * rstd * g[c] + b[c];
    }
}

// ---------------------------------------------------------------------------
// Head: logits[n][c] = x[n][W-1][:] . head_w[c][:] + head_b[c]. Warp per window.
// ---------------------------------------------------------------------------
__global__ void head_kernel(const float* __restrict__ hw,
                            const float* __restrict__ hb,
                            float* __restrict__ out) {
    __shared__ float hws[32][257];
    __shared__ float xs[8][256];
    int tid = threadIdx.x;
    for (int idx = tid; idx < 32 * 256; idx += 256) {
        int c = idx >> 8, d = idx & 255;
        hws[c][d] = hw[idx];
    }
    int warp = tid >> 5, lane = tid & 31;
    int n = blockIdx.x * 8 + warp;
    const float* xr = g_x + (size_t)(n * 32 + 31) * 256;
#pragma unroll
    for (int j = 0; j < 8; j++) xs[warp][lane + j * 32] = xr[lane + j * 32];
    __syncthreads();

    float accum = hb[lane];
#pragma unroll 8
    for (int d = 0; d < 256; d++) accum = fmaf(xs[warp][d], hws[lane][d], accum);
    out[(size_t)n * 32 + lane] = accum;
}

// ---------------------------------------------------------------------------
// Launch
// ---------------------------------------------------------------------------
extern "C" void kernel_launch(void* const* d_in, const int* in_sizes, int n_in,
                              void* d_out, int out_size) {
    const float* X    = (const float*)d_in[0];
    // d_in[1] action_seq (int64), d_in[2] mask (bool): unused by reference math
    const float* pos  = (const float*)d_in[3];
    const float* w_in = (const float*)d_in[4];
    const float* b_in = (const float*)d_in[5];
    const float* w_o  = (const float*)d_in[6];
    const float* b_o  = (const float*)d_in[7];
    const float* w1   = (const float*)d_in[8];
    const float* b1   = (const float*)d_in[9];
    const float* w2   = (const float*)d_in[10];
    const float* b2   = (const float*)d_in[11];
    const float* l1g  = (const float*)d_in[12];
    const float* l1b  = (const float*)d_in[13];
    const float* l2g  = (const float*)d_in[14];
    const float* l2b  = (const float*)d_in[15];
    const float* hw   = (const float*)d_in[16];
    const float* hb   = (const float*)d_in[17];
    float* out = (float*)d_out;

    void* p;
    cudaGetSymbolAddress(&p, g_x);   float* gx   = (float*)p;
    cudaGetSymbolAddress(&p, g_big); float* gbig = (float*)p;
    cudaGetSymbolAddress(&p, g_att); float* gatt = (float*)p;
    cudaGetSymbolAddress(&p, g_tmp); float* gtmp = (float*)p;

    gather_kernel<<<NTOK * 64 / 256, 256>>>(X, pos);

    for (int l = 0; l < 4; l++) {
        // QKV: (65536 x 768) = x @ Win^T
        sgemm_nt<false><<<dim3(768 / 128, NTOK / 128), 256>>>(
            gx, w_in + (size_t)l * 768 * 256, b_in + (size_t)l * 768, gbig,
            NTOK, 768, 256);
        // Attention per (window, head)
        attn_kernel<<<NWIN * 8, 128>>>(gbig);
        // Output projection: (65536 x 256)
        sgemm_nt<false><<<dim3(256 / 128, NTOK / 128), 256>>>(
            gatt, w_o + (size_t)l * 256 * 256, b_o + (size_t)l * 256, gtmp,
            NTOK, 256, 256);
        add_ln_kernel<<<NTOK / 8, 256>>>(gtmp, l1g + (size_t)l * 256,
                                         l1b + (size_t)l * 256);
        // FFN1 + ReLU: (65536 x 1024)
        sgemm_nt<true><<<dim3(1024 / 128, NTOK / 128), 256>>>(
            gx, w1 + (size_t)l * 1024 * 256, b1 + (size_t)l * 1024, gbig,
            NTOK, 1024, 256);
        // FFN2: (65536 x 256)
        sgemm_nt<false><<<dim3(256 / 128, NTOK / 128), 256>>>(
            gbig, w2 + (size_t)l * 256 * 1024, b2 + (size_t)l * 256, gtmp,
            NTOK, 256, 1024);
        add_ln_kernel<<<NTOK / 8, 256>>>(gtmp, l2g + (size_t)l * 256,
                                         l2b + (size_t)l * 256);
    }

    head_kernel<<<NWIN / 8, 256>>>(hw, hb, out);
}

// round 4
// speedup vs baseline: 1.8849x; 1.8849x over previous
#include <cuda_runtime.h>
#include <cuda_bf16.h>
#include <cstdint>

// ---------------------------------------------------------------------------
// SlidingWindowTransformer: B=4,S=512,D=256,W=32,L=4,H=8,DH=32,DFF=1024,NOUT=32
// Round 4: warp-level mma.sync bf16 (HMMA) with 2-term bf16 hi/lo split.
// Fix vs R3: B fragments use plain ldmatrix (K-major SMEM => k-consecutive
// pairs), not .trans (which delivered n-consecutive pairs -> rel_err 0.4).
// ---------------------------------------------------------------------------

namespace {
constexpr int Dm   = 256;
constexpr int DFF  = 1024;
constexpr int NWIN = 2048;            // B*S
constexpr int NTOK = NWIN * 32;       // 65536
constexpr float EPS   = 1e-5f;
constexpr float SCALE = 0.17677669529663687f;  // 32^-0.5
}

// Scratch (static device arrays; cudaMalloc forbidden).
__device__ float g_x  [(size_t)NTOK * Dm];
__device__ float g_big[(size_t)NTOK * DFF];
__device__ float g_att[(size_t)NTOK * Dm];
__device__ float g_tmp[(size_t)NTOK * Dm];

// ---------------------------------------------------------------------------
// MMA helpers
// ---------------------------------------------------------------------------
__device__ __forceinline__ void ldsm4(uint32_t* r, uint32_t addr) {
    asm volatile("ldmatrix.sync.aligned.m8n8.x4.shared.b16 {%0,%1,%2,%3}, [%4];"
                 : "=r"(r[0]), "=r"(r[1]), "=r"(r[2]), "=r"(r[3]) : "r"(addr));
}
__device__ __forceinline__ void mma16816(float* c, const uint32_t* a,
                                         uint32_t b0, uint32_t b1) {
    asm volatile(
        "mma.sync.aligned.m16n8k16.row.col.f32.bf16.bf16.f32 "
        "{%0,%1,%2,%3}, {%4,%5,%6,%7}, {%8,%9}, {%0,%1,%2,%3};"
        : "+f"(c[0]), "+f"(c[1]), "+f"(c[2]), "+f"(c[3])
        : "r"(a[0]), "r"(a[1]), "r"(a[2]), "r"(a[3]), "r"(b0), "r"(b1));
}
__device__ __forceinline__ uint32_t pack2(__nv_bfloat16 a, __nv_bfloat16 b) {
    __nv_bfloat162 t{a, b};
    return *reinterpret_cast<uint32_t*>(&t);
}
// 8 fp32 -> 8 bf16 hi (uint4) + 8 bf16 lo (uint4)
__device__ __forceinline__ void cvt_hilo8(const float* f, uint4& hi, uint4& lo) {
    __nv_bfloat16 h[8], l[8];
#pragma unroll
    for (int i = 0; i < 8; i++) {
        h[i] = __float2bfloat16(f[i]);
        l[i] = __float2bfloat16(f[i] - __bfloat162float(h[i]));
    }
    hi = make_uint4(pack2(h[0], h[1]), pack2(h[2], h[3]),
                    pack2(h[4], h[5]), pack2(h[6], h[7]));
    lo = make_uint4(pack2(l[0], l[1]), pack2(l[2], l[3]),
                    pack2(l[4], l[5]), pack2(l[6], l[7]));
}

// ---------------------------------------------------------------------------
// HMMA GEMM (NT): C[M,N] = A[M,K] @ Bw[N,K]^T + bias[N], optional ReLU.
// Tile 128x64, BK=32, 256 threads, warp tile 32x32.
// SMEM rows padded to 80B (5x16B, 5 coprime 8 => conflict-free ldmatrix).
// ---------------------------------------------------------------------------
template <bool RELU>
__global__ void __launch_bounds__(256, 2) mma_gemm(
    const float* __restrict__ A, const float* __restrict__ Bw,
    const float* __restrict__ bias, float* __restrict__ C,
    int K, int N)
{
    __shared__ uint4 sAhi[128 * 5];
    __shared__ uint4 sAlo[128 * 5];
    __shared__ uint4 sBhi[64 * 5];
    __shared__ uint4 sBlo[64 * 5];

    const int tid  = threadIdx.x;
    const int lane = tid & 31;
    const int wid  = tid >> 5;
    const int bm   = blockIdx.y * 128;
    const int bn   = blockIdx.x * 64;
    const int m0   = (wid >> 1) * 32;
    const int n0   = (wid & 1) * 32;

    // gmem load mapping: A thread -> (row=tid>>1, 16 floats at col (tid&1)*16)
    const int arow = tid >> 1, acol = (tid & 1) * 16;
    const int brow = tid >> 2, bcol = (tid & 3) * 8;
    const float* Ap = A + (size_t)(bm + arow) * K + acol;
    const float* Bp = Bw + (size_t)(bn + brow) * K + bcol;

    // ldmatrix addresses
    const uint32_t sAhiB = (uint32_t)__cvta_generic_to_shared(sAhi);
    const uint32_t sAloB = (uint32_t)__cvta_generic_to_shared(sAlo);
    const uint32_t sBhiB = (uint32_t)__cvta_generic_to_shared(sBhi);
    const uint32_t sBloB = (uint32_t)__cvta_generic_to_shared(sBlo);
    const int lrow = lane & 15;
    const int lch  = lane >> 4;
    uint32_t aHiAddr[2], aLoAddr[2], bHiAddr[2], bLoAddr[2];
#pragma unroll
    for (int i = 0; i < 2; i++) {
        uint32_t ao = (uint32_t)((m0 + i * 16 + lrow) * 80 + lch * 16);
        uint32_t bo = (uint32_t)((n0 + i * 16 + lrow) * 80 + lch * 16);
        aHiAddr[i] = sAhiB + ao; aLoAddr[i] = sAloB + ao;
        bHiAddr[i] = sBhiB + bo; bLoAddr[i] = sBloB + bo;
    }

    float c[2][4][4];
#pragma unroll
    for (int i = 0; i < 2; i++)
#pragma unroll
        for (int j = 0; j < 4; j++)
#pragma unroll
            for (int k = 0; k < 4; k++) c[i][j][k] = 0.f;

    // prologue loads
    float fa[16], fb[8];
#pragma unroll
    for (int i = 0; i < 4; i++)
        *reinterpret_cast<float4*>(&fa[i * 4]) =
            *reinterpret_cast<const float4*>(Ap + i * 4);
#pragma unroll
    for (int i = 0; i < 2; i++)
        *reinterpret_cast<float4*>(&fb[i * 4]) =
            *reinterpret_cast<const float4*>(Bp + i * 4);
    Ap += 32; Bp += 32;

    for (int kc = 0; kc < K; kc += 32) {
        // convert + store to smem
        {
            uint4 h0, l0, h1, l1, hb, lb;
            cvt_hilo8(fa, h0, l0);
            cvt_hilo8(fa + 8, h1, l1);
            cvt_hilo8(fb, hb, lb);
            int ai = arow * 5 + (acol >> 3);   // chunk index (16B units)
            sAhi[ai] = h0; sAhi[ai + 1] = h1;
            sAlo[ai] = l0; sAlo[ai + 1] = l1;
            int bi = brow * 5 + (bcol >> 3);
            sBhi[bi] = hb; sBlo[bi] = lb;
        }
        __syncthreads();

        if (kc + 32 < K) {   // prefetch next chunk into regs (hidden by mma)
#pragma unroll
            for (int i = 0; i < 4; i++)
                *reinterpret_cast<float4*>(&fa[i * 4]) =
                    *reinterpret_cast<const float4*>(Ap + i * 4);
#pragma unroll
            for (int i = 0; i < 2; i++)
                *reinterpret_cast<float4*>(&fb[i * 4]) =
                    *reinterpret_cast<const float4*>(Bp + i * 4);
            Ap += 32; Bp += 32;
        }

#pragma unroll
        for (int ks = 0; ks < 2; ks++) {
            const uint32_t ko = ks * 32;      // k16 step => +2 chunks => +32B
            uint32_t a[8], bh[8], bl[8];
            ldsm4(a + 0, aHiAddr[0] + ko);
            ldsm4(a + 4, aHiAddr[1] + ko);
            // B is K-major in SMEM: plain ldmatrix yields k-consecutive pairs
            ldsm4(bh + 0, bHiAddr[0] + ko);
            ldsm4(bh + 4, bHiAddr[1] + ko);
            ldsm4(bl + 0, bLoAddr[0] + ko);
            ldsm4(bl + 4, bLoAddr[1] + ko);
            // pass hh + hl
#pragma unroll
            for (int mi = 0; mi < 2; mi++)
#pragma unroll
                for (int j = 0; j < 4; j++) {
                    int g4 = (j >> 1) * 4, jj = j & 1;
                    mma16816(c[mi][j], a + mi * 4, bh[g4 + jj], bh[g4 + 2 + jj]);
                    mma16816(c[mi][j], a + mi * 4, bl[g4 + jj], bl[g4 + 2 + jj]);
                }
            // pass lh (A_lo overwrites a)
            ldsm4(a + 0, aLoAddr[0] + ko);
            ldsm4(a + 4, aLoAddr[1] + ko);
#pragma unroll
            for (int mi = 0; mi < 2; mi++)
#pragma unroll
                for (int j = 0; j < 4; j++) {
                    int g4 = (j >> 1) * 4, jj = j & 1;
                    mma16816(c[mi][j], a + mi * 4, bh[g4 + jj], bh[g4 + 2 + jj]);
                }
        }
        __syncthreads();
    }

    // epilogue: bias (+ReLU), fp32 stores
    const int g  = lane >> 2;
    const int t2 = lane & 3;
#pragma unroll
    for (int mi = 0; mi < 2; mi++) {
        int r0 = bm + m0 + mi * 16 + g;
#pragma unroll
        for (int j = 0; j < 4; j++) {
            int col = bn + n0 + j * 8 + t2 * 2;
            float2 bv = *reinterpret_cast<const float2*>(&bias[col]);
            float2 v0 = make_float2(c[mi][j][0] + bv.x, c[mi][j][1] + bv.y);
            float2 v1 = make_float2(c[mi][j][2] + bv.x, c[mi][j][3] + bv.y);
            if (RELU) {
                v0.x = fmaxf(v0.x, 0.f); v0.y = fmaxf(v0.y, 0.f);
                v1.x = fmaxf(v1.x, 0.f); v1.y = fmaxf(v1.y, 0.f);
            }
            *reinterpret_cast<float2*>(&C[(size_t)r0 * N + col]) = v0;
            *reinterpret_cast<float2*>(&C[(size_t)(r0 + 8) * N + col]) = v1;
        }
    }
}

// ---------------------------------------------------------------------------
// Gather: g_x[n][w][:] = X[b][clip(s-w,0)][:] + pos_embed[w][:]
// ---------------------------------------------------------------------------
__global__ void gather_kernel(const float* __restrict__ X,
                              const float* __restrict__ pos) {
    int idx = blockIdx.x * 256 + threadIdx.x;
    int d4 = idx & 63;
    int w  = (idx >> 6) & 31;
    int n  = idx >> 11;
    int s  = n & 511;
    int b  = n >> 9;
    int src = s - w; if (src < 0) src = 0;
    float4 xv = reinterpret_cast<const float4*>(X)[(size_t)(b * 512 + src) * 64 + d4];
    float4 pv = reinterpret_cast<const float4*>(pos)[(size_t)w * 64 + d4];
    reinterpret_cast<float4*>(g_x)[idx] =
        make_float4(xv.x + pv.x, xv.y + pv.y, xv.z + pv.z, xv.w + pv.w);
}

// ---------------------------------------------------------------------------
// Attention: one block per (window, head), W=32, DH=32, fp32.
// ---------------------------------------------------------------------------
__global__ void attn_kernel(const float* __restrict__ qkv) {
    int n = blockIdx.x >> 3;
    int h = blockIdx.x & 7;
    int tid = threadIdx.x;   // 128
    __shared__ float qs[32][32];
    __shared__ float ks[32][33];
    __shared__ float vs[32][33];
    __shared__ float ps[32][33];

    int bse = n * 32;
    int hc  = h * 32;
    for (int idx = tid; idx < 1024; idx += 128) {
        int i = idx >> 5, d = idx & 31;
        const float* row = qkv + (size_t)(bse + i) * 768;
        qs[i][d] = row[hc + d];
        ks[i][d] = row[256 + hc + d];
        vs[i][d] = row[512 + hc + d];
    }
    __syncthreads();
    for (int idx = tid; idx < 1024; idx += 128) {
        int i = idx >> 5, j = idx & 31;
        float s = 0.f;
#pragma unroll
        for (int d = 0; d < 32; d++) s = fmaf(qs[i][d], ks[j][d], s);
        ps[i][j] = s * SCALE;
    }
    __syncthreads();
    if (tid < 32) {
        float mx = -1e30f;
#pragma unroll
        for (int j = 0; j < 32; j++) mx = fmaxf(mx, ps[tid][j]);
        float sum = 0.f;
#pragma unroll
        for (int j = 0; j < 32; j++) {
            float e = __expf(ps[tid][j] - mx);
            ps[tid][j] = e;
            sum += e;
        }
        float inv = 1.f / sum;
#pragma unroll
        for (int j = 0; j < 32; j++) ps[tid][j] *= inv;
    }
    __syncthreads();
    for (int idx = tid; idx < 1024; idx += 128) {
        int i = idx >> 5, d = idx & 31;
        float s = 0.f;
#pragma unroll
        for (int j = 0; j < 32; j++) s = fmaf(ps[i][j], vs[j][d], s);
        g_att[(size_t)(bse + i) * 256 + hc + d] = s;
    }
}

// ---------------------------------------------------------------------------
// Residual add + LayerNorm, in-place on g_x. Warp per token.
// ---------------------------------------------------------------------------
__global__ void add_ln_kernel(const float* __restrict__ y,
                              const float* __restrict__ g,
                              const float* __restrict__ b) {
    int warp  = threadIdx.x >> 5;
    int lane  = threadIdx.x & 31;
    int token = blockIdx.x * 8 + warp;
    float* xr = g_x + (size_t)token * 256;
    const float* yr = y + (size_t)token * 256;

    float v[8];
    float s = 0.f;
#pragma unroll
    for (int j = 0; j < 8; j++) {
        int c = lane + j * 32;
        v[j] = xr[c] + yr[c];
        s += v[j];
    }
#pragma unroll
    for (int o = 16; o > 0; o >>= 1) s += __shfl_xor_sync(0xffffffffu, s, o);
    float mu = s * (1.f / 256.f);
    float s2 = 0.f;
#pragma unroll
    for (int j = 0; j < 8; j++) { float d = v[j] - mu; s2 += d * d; }
#pragma unroll
    for (int o = 16; o > 0; o >>= 1) s2 += __shfl_xor_sync(0xffffffffu, s2, o);
    float rstd = rsqrtf(s2 * (1.f / 256.f) + EPS);
#pragma unroll
    for (int j = 0; j < 8; j++) {
        int c = lane + j * 32;
        xr[c] = (v[j] - mu) * rstd * g[c] + b[c];
    }
}

// ---------------------------------------------------------------------------
// Head: logits[n][c] = x[n][31][:] . head_w[c][:] + head_b[c]. Warp per window.
// ---------------------------------------------------------------------------
__global__ void head_kernel(const float* __restrict__ hw,
                            const float* __restrict__ hb,
                            float* __restrict__ out) {
    __shared__ float hws[32][257];
    __shared__ float xs[8][256];
    int tid = threadIdx.x;
    for (int idx = tid; idx < 32 * 256; idx += 256) {
        int c = idx >> 8, d = idx & 255;
        hws[c][d] = hw[idx];
    }
    int warp = tid >> 5, lane = tid & 31;
    int n = blockIdx.x * 8 + warp;
    const float* xr = g_x + (size_t)(n * 32 + 31) * 256;
#pragma unroll
    for (int j = 0; j < 8; j++) xs[warp][lane + j * 32] = xr[lane + j * 32];
    __syncthreads();

    float accum = hb[lane];
#pragma unroll 8
    for (int d = 0; d < 256; d++) accum = fmaf(xs[warp][d], hws[lane][d], accum);
    out[(size_t)n * 32 + lane] = accum;
}

// ---------------------------------------------------------------------------
// Launch
// ---------------------------------------------------------------------------
extern "C" void kernel_launch(void* const* d_in, const int* in_sizes, int n_in,
                              void* d_out, int out_size) {
    const float* X    = (const float*)d_in[0];
    const float* pos  = (const float*)d_in[3];
    const float* w_in = (const float*)d_in[4];
    const float* b_in = (const float*)d_in[5];
    const float* w_o  = (const float*)d_in[6];
    const float* b_o  = (const float*)d_in[7];
    const float* w1   = (const float*)d_in[8];
    const float* b1   = (const float*)d_in[9];
    const float* w2   = (const float*)d_in[10];
    const float* b2   = (const float*)d_in[11];
    const float* l1g  = (const float*)d_in[12];
    const float* l1b  = (const float*)d_in[13];
    const float* l2g  = (const float*)d_in[14];
    const float* l2b  = (const float*)d_in[15];
    const float* hw   = (const float*)d_in[16];
    const float* hb   = (const float*)d_in[17];
    float* out = (float*)d_out;

    void* p;
    cudaGetSymbolAddress(&p, g_x);   float* gx   = (float*)p;
    cudaGetSymbolAddress(&p, g_big); float* gbig = (float*)p;
    cudaGetSymbolAddress(&p, g_att); float* gatt = (float*)p;
    cudaGetSymbolAddress(&p, g_tmp); float* gtmp = (float*)p;

    gather_kernel<<<NTOK * 64 / 256, 256>>>(X, pos);

    for (int l = 0; l < 4; l++) {
        // QKV: (65536 x 768), K=256
        mma_gemm<false><<<dim3(12, 512), 256>>>(
            gx, w_in + (size_t)l * 768 * 256, b_in + (size_t)l * 768, gbig,
            256, 768);
        attn_kernel<<<NWIN * 8, 128>>>(gbig);
        // o-proj: (65536 x 256), K=256
        mma_gemm<false><<<dim3(4, 512), 256>>>(
            gatt, w_o + (size_t)l * 256 * 256, b_o + (size_t)l * 256, gtmp,
            256, 256);
        add_ln_kernel<<<NTOK / 8, 256>>>(gtmp, l1g + (size_t)l * 256,
                                         l1b + (size_t)l * 256);
        // FFN1 + ReLU: (65536 x 1024), K=256
        mma_gemm<true><<<dim3(16, 512), 256>>>(
            gx, w1 + (size_t)l * 1024 * 256, b1 + (size_t)l * 1024, gbig,
            256, 1024);
        // FFN2: (65536 x 256), K=1024
        mma_gemm<false><<<dim3(4, 512), 256>>>(
            gbig, w2 + (size_t)l * 256 * 1024, b2 + (size_t)l * 256, gtmp,
            1024, 256);
        add_ln_kernel<<<NTOK / 8, 256>>>(gtmp, l2g + (size_t)l * 256,
                                         l2b + (size_t)l * 256);
    }

    head_kernel<<<NWIN / 8, 256>>>(hw, hb, out);
}

// round 6
// speedup vs baseline: 2.0774x; 1.1021x over previous
#include <cuda_runtime.h>
#include <cuda_bf16.h>
#include <cstdint>

// ---------------------------------------------------------------------------
// SlidingWindowTransformer: B=4,S=512,D=256,W=32,L=4,H=8,DH=32,DFF=1024,NOUT=32
// Round 6 (= Round 5 resubmit; prior bench was an infra failure):
//  - GEMM v2: CTA 128x128, 8 warps (2Mx4N), warp tile 64x32, cp.async 2-stage
//    pipeline, all operands pre-converted to bf16 hi/lo (zero in-GEMM cvt).
//  - attn v2: register-cached q, K^T smem layout, float4 LDS, register softmax.
//  - Producers (gather / add_ln / attn / FFN1 epilogue) emit bf16 hi/lo.
// ---------------------------------------------------------------------------

namespace {
constexpr int Dm   = 256;
constexpr int DFF  = 1024;
constexpr int NWIN = 2048;            // B*S
constexpr int NTOK = NWIN * 32;       // 65536
constexpr float EPS   = 1e-5f;
constexpr float SCALE = 0.17677669529663687f;  // 32^-0.5
constexpr int GSMEM = 2 * 40960;      // 2 stages x (4 tiles x 10240B)
}

// fp32 scratch
__device__ float g_x  [(size_t)NTOK * Dm];     // activations (residual base)
__device__ float g_qkv[(size_t)NTOK * 768];    // QKV gemm output (fp32 for attn)
__device__ float g_tmp[(size_t)NTOK * Dm];     // o-proj / ffn2 fp32 outputs
// bf16 hi/lo activation scratch
__device__ __nv_bfloat16 g_xh[(size_t)NTOK * Dm];
__device__ __nv_bfloat16 g_xl[(size_t)NTOK * Dm];
__device__ __nv_bfloat16 g_ah[(size_t)NTOK * Dm];
__device__ __nv_bfloat16 g_al[(size_t)NTOK * Dm];
__device__ __nv_bfloat16 g_fh[(size_t)NTOK * DFF];
__device__ __nv_bfloat16 g_fl[(size_t)NTOK * DFF];
// bf16 hi/lo weights (pre-converted each replay; cheap + deterministic)
__device__ __nv_bfloat16 g_winh[4 * 768 * 256],  g_winl[4 * 768 * 256];
__device__ __nv_bfloat16 g_woh [4 * 256 * 256],  g_wol [4 * 256 * 256];
__device__ __nv_bfloat16 g_w1h [4 * 1024 * 256], g_w1l [4 * 1024 * 256];
__device__ __nv_bfloat16 g_w2h [4 * 256 * 1024], g_w2l [4 * 256 * 1024];

// ---------------------------------------------------------------------------
// helpers
// ---------------------------------------------------------------------------
__device__ __forceinline__ void ldsm4(uint32_t* r, uint32_t addr) {
    asm volatile("ldmatrix.sync.aligned.m8n8.x4.shared.b16 {%0,%1,%2,%3}, [%4];"
                 : "=r"(r[0]), "=r"(r[1]), "=r"(r[2]), "=r"(r[3]) : "r"(addr));
}
__device__ __forceinline__ void mma16816(float* c, const uint32_t* a,
                                         uint32_t b0, uint32_t b1) {
    asm volatile(
        "mma.sync.aligned.m16n8k16.row.col.f32.bf16.bf16.f32 "
        "{%0,%1,%2,%3}, {%4,%5,%6,%7}, {%8,%9}, {%0,%1,%2,%3};"
        : "+f"(c[0]), "+f"(c[1]), "+f"(c[2]), "+f"(c[3])
        : "r"(a[0]), "r"(a[1]), "r"(a[2]), "r"(a[3]), "r"(b0), "r"(b1));
}
__device__ __forceinline__ void cp_async16(uint32_t dst, const void* src) {
    asm volatile("cp.async.cg.shared.global [%0], [%1], 16;"
                 :: "r"(dst), "l"(src) : "memory");
}
__device__ __forceinline__ uint32_t pack2(__nv_bfloat16 a, __nv_bfloat16 b) {
    __nv_bfloat162 t{a, b};
    return *reinterpret_cast<uint32_t*>(&t);
}
__device__ __forceinline__ void split2(float x, float y,
                                       uint32_t& hi, uint32_t& lo) {
    __nv_bfloat16 hx = __float2bfloat16(x);
    __nv_bfloat16 hy = __float2bfloat16(y);
    __nv_bfloat16 lx = __float2bfloat16(x - __bfloat162float(hx));
    __nv_bfloat16 ly = __float2bfloat16(y - __bfloat162float(hy));
    hi = pack2(hx, hy);
    lo = pack2(lx, ly);
}

// ---------------------------------------------------------------------------
// Weight prep: fp32 -> bf16 hi/lo
// ---------------------------------------------------------------------------
__global__ void prep_kernel(const float* __restrict__ src,
                            __nv_bfloat16* __restrict__ dh,
                            __nv_bfloat16* __restrict__ dl, int n) {
    int i = blockIdx.x * 256 + threadIdx.x;
    if (i >= n) return;
    float v = src[i];
    __nv_bfloat16 h = __float2bfloat16(v);
    dh[i] = h;
    dl[i] = __float2bfloat16(v - __bfloat162float(h));
}

// ---------------------------------------------------------------------------
// GEMM v2 (NT): C[M,N] = (Ah+Al)[M,K] @ (Bh+Bl)[N,K]^T + bias[N]
// MODE 0: fp32 out.  MODE 3: ReLU then bf16 hi/lo out.
// CTA 128x128, BK=32, 8 warps (2Mx4N), warp tile 64x32, cp.async 2-stage.
// SMEM per stage: Ah@0, Al@10240, Bh@20480, Bl@30720 (rows padded to 80B).
// ---------------------------------------------------------------------------
template <int MODE>
__global__ void __launch_bounds__(256, 2) mma_gemm2(
    const __nv_bfloat16* __restrict__ Ah, const __nv_bfloat16* __restrict__ Al,
    const __nv_bfloat16* __restrict__ Bh, const __nv_bfloat16* __restrict__ Bl,
    const float* __restrict__ bias,
    float* __restrict__ C,
    __nv_bfloat16* __restrict__ Ch, __nv_bfloat16* __restrict__ Cl,
    int K, int N)
{
    extern __shared__ char smem[];
    const uint32_t sb0 = (uint32_t)__cvta_generic_to_shared(smem);

    const int tid  = threadIdx.x;
    const int lane = tid & 31;
    const int wid  = tid >> 5;
    const int bm   = blockIdx.y * 128;
    const int bn   = blockIdx.x * 128;
    const int m0   = (wid >> 2) * 64;
    const int n0   = (wid & 3) * 32;

    const int lrow = lane & 15;
    const int lch  = lane >> 4;
    uint32_t aOff[4], bOff[2];
#pragma unroll
    for (int i = 0; i < 4; i++)
        aOff[i] = (uint32_t)((m0 + i * 16 + lrow) * 80 + lch * 16);
#pragma unroll
    for (int i = 0; i < 2; i++)
        bOff[i] = (uint32_t)((n0 + i * 16 + lrow) * 80 + lch * 16);

    float c[4][4][4];
#pragma unroll
    for (int i = 0; i < 4; i++)
#pragma unroll
        for (int j = 0; j < 4; j++)
#pragma unroll
            for (int k = 0; k < 4; k++) c[i][j][k] = 0.f;

    auto load_stage = [&](int s, int k0) {
        uint32_t base = sb0 + s * 40960;
#pragma unroll
        for (int i = 0; i < 2; i++) {
            int cc  = tid + i * 256;        // chunk id 0..511
            int row = cc >> 2;
            int kc  = cc & 3;
            uint32_t d = base + (uint32_t)(row * 80 + kc * 16);
            size_t ao = (size_t)(bm + row) * K + k0 + kc * 8;
            size_t bo = (size_t)(bn + row) * K + k0 + kc * 8;
            cp_async16(d,         Ah + ao);
            cp_async16(d + 10240, Al + ao);
            cp_async16(d + 20480, Bh + bo);
            cp_async16(d + 30720, Bl + bo);
        }
        asm volatile("cp.async.commit_group;" ::: "memory");
    };

    load_stage(0, 0);
    const int ntile = K >> 5;
    for (int it = 0; it < ntile; it++) {
        if (it + 1 < ntile) {
            load_stage((it + 1) & 1, (it + 1) * 32);
            asm volatile("cp.async.wait_group 1;" ::: "memory");
        } else {
            asm volatile("cp.async.wait_group 0;" ::: "memory");
        }
        __syncthreads();

        uint32_t base = sb0 + (it & 1) * 40960;
#pragma unroll
        for (int ks = 0; ks < 2; ks++) {
            const uint32_t ko = ks * 32;
            uint32_t a[16], bh[8], bl[8];
            ldsm4(a + 0,  base + aOff[0] + ko);
            ldsm4(a + 4,  base + aOff[1] + ko);
            ldsm4(a + 8,  base + aOff[2] + ko);
            ldsm4(a + 12, base + aOff[3] + ko);
            ldsm4(bh + 0, base + 20480 + bOff[0] + ko);
            ldsm4(bh + 4, base + 20480 + bOff[1] + ko);
            ldsm4(bl + 0, base + 30720 + bOff[0] + ko);
            ldsm4(bl + 4, base + 30720 + bOff[1] + ko);
            // A_hi * (B_hi + B_lo)
#pragma unroll
            for (int mi = 0; mi < 4; mi++)
#pragma unroll
                for (int j = 0; j < 4; j++) {
                    int g4 = (j >> 1) * 4, jj = j & 1;
                    mma16816(c[mi][j], a + mi * 4, bh[g4 + jj], bh[g4 + 2 + jj]);
                    mma16816(c[mi][j], a + mi * 4, bl[g4 + jj], bl[g4 + 2 + jj]);
                }
            // A_lo * B_hi
            ldsm4(a + 0,  base + 10240 + aOff[0] + ko);
            ldsm4(a + 4,  base + 10240 + aOff[1] + ko);
            ldsm4(a + 8,  base + 10240 + aOff[2] + ko);
            ldsm4(a + 12, base + 10240 + aOff[3] + ko);
#pragma unroll
            for (int mi = 0; mi < 4; mi++)
#pragma unroll
                for (int j = 0; j < 4; j++) {
                    int g4 = (j >> 1) * 4, jj = j & 1;
                    mma16816(c[mi][j], a + mi * 4, bh[g4 + jj], bh[g4 + 2 + jj]);
                }
        }
        __syncthreads();
    }

    // epilogue
    const int g  = lane >> 2;
    const int t2 = lane & 3;
#pragma unroll
    for (int mi = 0; mi < 4; mi++) {
        int r0 = bm + m0 + mi * 16 + g;
#pragma unroll
        for (int j = 0; j < 4; j++) {
            int col = bn + n0 + j * 8 + t2 * 2;
            float2 bv = *reinterpret_cast<const float2*>(&bias[col]);
            float v0x = c[mi][j][0] + bv.x, v0y = c[mi][j][1] + bv.y;
            float v1x = c[mi][j][2] + bv.x, v1y = c[mi][j][3] + bv.y;
            if (MODE == 0) {
                *reinterpret_cast<float2*>(&C[(size_t)r0 * N + col]) =
                    make_float2(v0x, v0y);
                *reinterpret_cast<float2*>(&C[(size_t)(r0 + 8) * N + col]) =
                    make_float2(v1x, v1y);
            } else {
                v0x = fmaxf(v0x, 0.f); v0y = fmaxf(v0y, 0.f);
                v1x = fmaxf(v1x, 0.f); v1y = fmaxf(v1y, 0.f);
                uint32_t h0, l0, h1, l1;
                split2(v0x, v0y, h0, l0);
                split2(v1x, v1y, h1, l1);
                *reinterpret_cast<uint32_t*>(&Ch[(size_t)r0 * N + col])       = h0;
                *reinterpret_cast<uint32_t*>(&Cl[(size_t)r0 * N + col])       = l0;
                *reinterpret_cast<uint32_t*>(&Ch[(size_t)(r0 + 8) * N + col]) = h1;
                *reinterpret_cast<uint32_t*>(&Cl[(size_t)(r0 + 8) * N + col]) = l1;
            }
        }
    }
}

// ---------------------------------------------------------------------------
// Gather: g_x fp32 + hi/lo copies
// ---------------------------------------------------------------------------
__global__ void gather_kernel(const float* __restrict__ X,
                              const float* __restrict__ pos) {
    int idx = blockIdx.x * 256 + threadIdx.x;  // float4 index over NTOK*64
    int d4 = idx & 63;
    int w  = (idx >> 6) & 31;
    int n  = idx >> 11;
    int s  = n & 511;
    int b  = n >> 9;
    int src = s - w; if (src < 0) src = 0;
    float4 xv = reinterpret_cast<const float4*>(X)[(size_t)(b * 512 + src) * 64 + d4];
    float4 pv = reinterpret_cast<const float4*>(pos)[(size_t)w * 64 + d4];
    float4 o  = make_float4(xv.x + pv.x, xv.y + pv.y, xv.z + pv.z, xv.w + pv.w);
    reinterpret_cast<float4*>(g_x)[idx] = o;
    uint32_t h0, l0, h1, l1;
    split2(o.x, o.y, h0, l0);
    split2(o.z, o.w, h1, l1);
    *reinterpret_cast<uint2*>(&g_xh[(size_t)idx * 4]) = make_uint2(h0, h1);
    *reinterpret_cast<uint2*>(&g_xl[(size_t)idx * 4]) = make_uint2(l0, l1);
}

// ---------------------------------------------------------------------------
// Attention v2: block = (window, head), 128 threads.
// K stored transposed; float4 LDS; register softmax over 4-lane groups.
// Writes bf16 hi/lo for the o-proj GEMM.
// ---------------------------------------------------------------------------
__global__ void attn_kernel2(const float* __restrict__ qkv,
                             __nv_bfloat16* __restrict__ oh,
                             __nv_bfloat16* __restrict__ ol) {
    __shared__ float qs[32][36];
    __shared__ float kT[32][36];   // kT[d][token]
    __shared__ float vs[32][36];
    __shared__ float ps[32][36];

    const int n   = blockIdx.x >> 3;
    const int h   = blockIdx.x & 7;
    const int tid = threadIdx.x;
    const int bse = n * 32;
    const int hc  = h * 32;

    for (int idx = tid; idx < 768; idx += 128) {
        int r = idx >> 3, c4 = idx & 7;
        int sect = r >> 5, tok = r & 31;
        float4 v = *reinterpret_cast<const float4*>(
            qkv + (size_t)(bse + tok) * 768 + sect * 256 + hc + c4 * 4);
        if (sect == 0) {
            *reinterpret_cast<float4*>(&qs[tok][c4 * 4]) = v;
        } else if (sect == 1) {
            kT[c4 * 4 + 0][tok] = v.x; kT[c4 * 4 + 1][tok] = v.y;
            kT[c4 * 4 + 2][tok] = v.z; kT[c4 * 4 + 3][tok] = v.w;
        } else {
            *reinterpret_cast<float4*>(&vs[tok][c4 * 4]) = v;
        }
    }
    __syncthreads();

    const int i  = tid >> 2;
    const int jc = tid & 3;

    // scores: row i, cols jc*8..+7
    float q[32];
#pragma unroll
    for (int u = 0; u < 8; u++) {
        float4 t = *reinterpret_cast<const float4*>(&qs[i][u * 4]);
        q[u * 4 + 0] = t.x * SCALE; q[u * 4 + 1] = t.y * SCALE;
        q[u * 4 + 2] = t.z * SCALE; q[u * 4 + 3] = t.w * SCALE;
    }
    float acc[8];
#pragma unroll
    for (int u = 0; u < 8; u++) acc[u] = 0.f;
#pragma unroll
    for (int d = 0; d < 32; d++) {
        float4 k0 = *reinterpret_cast<const float4*>(&kT[d][jc * 8]);
        float4 k1 = *reinterpret_cast<const float4*>(&kT[d][jc * 8 + 4]);
        float qd = q[d];
        acc[0] = fmaf(qd, k0.x, acc[0]); acc[1] = fmaf(qd, k0.y, acc[1]);
        acc[2] = fmaf(qd, k0.z, acc[2]); acc[3] = fmaf(qd, k0.w, acc[3]);
        acc[4] = fmaf(qd, k1.x, acc[4]); acc[5] = fmaf(qd, k1.y, acc[5]);
        acc[6] = fmaf(qd, k1.z, acc[6]); acc[7] = fmaf(qd, k1.w, acc[7]);
    }
    // softmax across the 4-lane group (32 values)
    float mx = acc[0];
#pragma unroll
    for (int u = 1; u < 8; u++) mx = fmaxf(mx, acc[u]);
    mx = fmaxf(mx, __shfl_xor_sync(0xffffffffu, mx, 1));
    mx = fmaxf(mx, __shfl_xor_sync(0xffffffffu, mx, 2));
    float sum = 0.f;
#pragma unroll
    for (int u = 0; u < 8; u++) { acc[u] = __expf(acc[u] - mx); sum += acc[u]; }
    sum += __shfl_xor_sync(0xffffffffu, sum, 1);
    sum += __shfl_xor_sync(0xffffffffu, sum, 2);
    float inv = 1.f / sum;
#pragma unroll
    for (int u = 0; u < 8; u++) acc[u] *= inv;
    *reinterpret_cast<float4*>(&ps[i][jc * 8]) =
        make_float4(acc[0], acc[1], acc[2], acc[3]);
    *reinterpret_cast<float4*>(&ps[i][jc * 8 + 4]) =
        make_float4(acc[4], acc[5], acc[6], acc[7]);
    __syncthreads();

    // AV: row i, dims jc*8..+7
    float o[8];
#pragma unroll
    for (int u = 0; u < 8; u++) o[u] = 0.f;
#pragma unroll
    for (int j = 0; j < 32; j++) {
        float pj = ps[i][j];
        float4 v0 = *reinterpret_cast<const float4*>(&vs[j][jc * 8]);
        float4 v1 = *reinterpret_cast<const float4*>(&vs[j][jc * 8 + 4]);
        o[0] = fmaf(pj, v0.x, o[0]); o[1] = fmaf(pj, v0.y, o[1]);
        o[2] = fmaf(pj, v0.z, o[2]); o[3] = fmaf(pj, v0.w, o[3]);
        o[4] = fmaf(pj, v1.x, o[4]); o[5] = fmaf(pj, v1.y, o[5]);
        o[6] = fmaf(pj, v1.z, o[6]); o[7] = fmaf(pj, v1.w, o[7]);
    }
    uint32_t hp[4], lp[4];
    split2(o[0], o[1], hp[0], lp[0]);
    split2(o[2], o[3], hp[1], lp[1]);
    split2(o[4], o[5], hp[2], lp[2]);
    split2(o[6], o[7], hp[3], lp[3]);
    size_t base = (size_t)(bse + i) * 256 + hc + jc * 8;
    *reinterpret_cast<uint4*>(&oh[base]) = make_uint4(hp[0], hp[1], hp[2], hp[3]);
    *reinterpret_cast<uint4*>(&ol[base]) = make_uint4(lp[0], lp[1], lp[2], lp[3]);
}

// ---------------------------------------------------------------------------
// Residual add + LayerNorm: updates g_x fp32 and writes hi/lo copies.
// Warp per token, lane owns 8 contiguous cols.
// ---------------------------------------------------------------------------
__global__ void add_ln_kernel(const float* __restrict__ y,
                              const float* __restrict__ gg,
                              const float* __restrict__ bb) {
    int warp  = threadIdx.x >> 5;
    int lane  = threadIdx.x & 31;
    int token = blockIdx.x * 8 + warp;
    int c0    = lane * 8;
    float* xr = g_x + (size_t)token * 256;
    const float* yr = y + (size_t)token * 256;

    float v[8];
    float4 x0 = *reinterpret_cast<const float4*>(xr + c0);
    float4 x1 = *reinterpret_cast<const float4*>(xr + c0 + 4);
    float4 y0 = *reinterpret_cast<const float4*>(yr + c0);
    float4 y1 = *reinterpret_cast<const float4*>(yr + c0 + 4);
    v[0] = x0.x + y0.x; v[1] = x0.y + y0.y; v[2] = x0.z + y0.z; v[3] = x0.w + y0.w;
    v[4] = x1.x + y1.x; v[5] = x1.y + y1.y; v[6] = x1.z + y1.z; v[7] = x1.w + y1.w;

    float s = 0.f;
#pragma unroll
    for (int j = 0; j < 8; j++) s += v[j];
#pragma unroll
    for (int o = 16; o > 0; o >>= 1) s += __shfl_xor_sync(0xffffffffu, s, o);
    float mu = s * (1.f / 256.f);
    float s2 = 0.f;
#pragma unroll
    for (int j = 0; j < 8; j++) { float d = v[j] - mu; s2 += d * d; }
#pragma unroll
    for (int o = 16; o > 0; o >>= 1) s2 += __shfl_xor_sync(0xffffffffu, s2, o);
    float rstd = rsqrtf(s2 * (1.f / 256.f) + EPS);

    float4 g0 = *reinterpret_cast<const float4*>(gg + c0);
    float4 g1 = *reinterpret_cast<const float4*>(gg + c0 + 4);
    float4 b0 = *reinterpret_cast<const float4*>(bb + c0);
    float4 b1 = *reinterpret_cast<const float4*>(bb + c0 + 4);
    float r[8];
    r[0] = (v[0] - mu) * rstd * g0.x + b0.x; r[1] = (v[1] - mu) * rstd * g0.y + b0.y;
    r[2] = (v[2] - mu) * rstd * g0.z + b0.z; r[3] = (v[3] - mu) * rstd * g0.w + b0.w;
    r[4] = (v[4] - mu) * rstd * g1.x + b1.x; r[5] = (v[5] - mu) * rstd * g1.y + b1.y;
    r[6] = (v[6] - mu) * rstd * g1.z + b1.z; r[7] = (v[7] - mu) * rstd * g1.w + b1.w;

    *reinterpret_cast<float4*>(xr + c0)     = make_float4(r[0], r[1], r[2], r[3]);
    *reinterpret_cast<float4*>(xr + c0 + 4) = make_float4(r[4], r[5], r[6], r[7]);
    uint32_t hp[4], lp[4];
    split2(r[0], r[1], hp[0], lp[0]);
    split2(r[2], r[3], hp[1], lp[1]);
    split2(r[4], r[5], hp[2], lp[2]);
    split2(r[6], r[7], hp[3], lp[3]);
    size_t base = (size_t)token * 256 + c0;
    *reinterpret_cast<uint4*>(&g_xh[base]) = make_uint4(hp[0], hp[1], hp[2], hp[3]);
    *reinterpret_cast<uint4*>(&g_xl[base]) = make_uint4(lp[0], lp[1], lp[2], lp[3]);
}

// ---------------------------------------------------------------------------
// Head: logits[n][c] = x[n][31][:] . head_w[c][:] + head_b[c]. Warp per window.
// ---------------------------------------------------------------------------
__global__ void head_kernel(const float* __restrict__ hw,
                            const float* __restrict__ hb,
                            float* __restrict__ out) {
    __shared__ float hws[32][257];
    __shared__ float xs[8][256];
    int tid = threadIdx.x;
    for (int idx = tid; idx < 32 * 256; idx += 256) {
        int c = idx >> 8, d = idx & 255;
        hws[c][d] = hw[idx];
    }
    int warp = tid >> 5, lane = tid & 31;
    int n = blockIdx.x * 8 + warp;
    const float* xr = g_x + (size_t)(n * 32 + 31) * 256;
#pragma unroll
    for (int j = 0; j < 8; j++) xs[warp][lane + j * 32] = xr[lane + j * 32];
    __syncthreads();

    float accum = hb[lane];
#pragma unroll 8
    for (int d = 0; d < 256; d++) accum = fmaf(xs[warp][d], hws[lane][d], accum);
    out[(size_t)n * 32 + lane] = accum;
}

// ---------------------------------------------------------------------------
// Launch
// ---------------------------------------------------------------------------
extern "C" void kernel_launch(void* const* d_in, const int* in_sizes, int n_in,
                              void* d_out, int out_size) {
    const float* X    = (const float*)d_in[0];
    const float* pos  = (const float*)d_in[3];
    const float* w_in = (const float*)d_in[4];
    const float* b_in = (const float*)d_in[5];
    const float* w_o  = (const float*)d_in[6];
    const float* b_o  = (const float*)d_in[7];
    const float* w1   = (const float*)d_in[8];
    const float* b1   = (const float*)d_in[9];
    const float* w2   = (const float*)d_in[10];
    const float* b2   = (const float*)d_in[11];
    const float* l1g  = (const float*)d_in[12];
    const float* l1b  = (const float*)d_in[13];
    const float* l2g  = (const float*)d_in[14];
    const float* l2b  = (const float*)d_in[15];
    const float* hw   = (const float*)d_in[16];
    const float* hb   = (const float*)d_in[17];
    float* out = (float*)d_out;

    void* p;
    typedef __nv_bfloat16 bf;
    cudaGetSymbolAddress(&p, g_qkv);  float* qkv = (float*)p;
    cudaGetSymbolAddress(&p, g_tmp);  float* tmp = (float*)p;
    cudaGetSymbolAddress(&p, g_xh);   bf* xh = (bf*)p;
    cudaGetSymbolAddress(&p, g_xl);   bf* xl = (bf*)p;
    cudaGetSymbolAddress(&p, g_ah);   bf* ah = (bf*)p;
    cudaGetSymbolAddress(&p, g_al);   bf* al = (bf*)p;
    cudaGetSymbolAddress(&p, g_fh);   bf* fh = (bf*)p;
    cudaGetSymbolAddress(&p, g_fl);   bf* fl = (bf*)p;
    cudaGetSymbolAddress(&p, g_winh); bf* winh = (bf*)p;
    cudaGetSymbolAddress(&p, g_winl); bf* winl = (bf*)p;
    cudaGetSymbolAddress(&p, g_woh);  bf* woh = (bf*)p;
    cudaGetSymbolAddress(&p, g_wol);  bf* wol = (bf*)p;
    cudaGetSymbolAddress(&p, g_w1h);  bf* w1h = (bf*)p;
    cudaGetSymbolAddress(&p, g_w1l);  bf* w1l = (bf*)p;
    cudaGetSymbolAddress(&p, g_w2h);  bf* w2h = (bf*)p;
    cudaGetSymbolAddress(&p, g_w2l);  bf* w2l = (bf*)p;

    cudaFuncSetAttribute(mma_gemm2<0>,
        cudaFuncAttributeMaxDynamicSharedMemorySize, GSMEM);
    cudaFuncSetAttribute(mma_gemm2<3>,
        cudaFuncAttributeMaxDynamicSharedMemorySize, GSMEM);

    // weight prep (cheap; runs each replay, deterministic)
    prep_kernel<<<(4 * 768 * 256 + 255) / 256, 256>>>(w_in, winh, winl, 4 * 768 * 256);
    prep_kernel<<<(4 * 256 * 256 + 255) / 256, 256>>>(w_o, woh, wol, 4 * 256 * 256);
    prep_kernel<<<(4 * 1024 * 256 + 255) / 256, 256>>>(w1, w1h, w1l, 4 * 1024 * 256);
    prep_kernel<<<(4 * 256 * 1024 + 255) / 256, 256>>>(w2, w2h, w2l, 4 * 256 * 1024);

    gather_kernel<<<NTOK * 64 / 256, 256>>>(X, pos);

    for (int l = 0; l < 4; l++) {
        // QKV: (65536 x 768), K=256, fp32 out for attn
        mma_gemm2<0><<<dim3(6, 512), 256, GSMEM>>>(
            xh, xl, winh + (size_t)l * 768 * 256, winl + (size_t)l * 768 * 256,
            b_in + (size_t)l * 768, qkv, nullptr, nullptr, 256, 768);
        attn_kernel2<<<NWIN * 8, 128>>>(qkv, ah, al);
        // o-proj: (65536 x 256), K=256, fp32 out (residual add)
        mma_gemm2<0><<<dim3(2, 512), 256, GSMEM>>>(
            ah, al, woh + (size_t)l * 256 * 256, wol + (size_t)l * 256 * 256,
            b_o + (size_t)l * 256, tmp, nullptr, nullptr, 256, 256);
        add_ln_kernel<<<NTOK / 8, 256>>>(tmp, l1g + (size_t)l * 256,
                                         l1b + (size_t)l * 256);
        // FFN1: (65536 x 1024), K=256, ReLU + hi/lo out
        mma_gemm2<3><<<dim3(8, 512), 256, GSMEM>>>(
            xh, xl, w1h + (size_t)l * 1024 * 256, w1l + (size_t)l * 1024 * 256,
            b1 + (size_t)l * 1024, nullptr, fh, fl, 256, 1024);
        // FFN2: (65536 x 256), K=1024, fp32 out
        mma_gemm2<0><<<dim3(2, 512), 256, GSMEM>>>(
            fh, fl, w2h + (size_t)l * 256 * 1024, w2l + (size_t)l * 256 * 1024,
            b2 + (size_t)l * 256, tmp, nullptr, nullptr, 1024, 256);
        add_ln_kernel<<<NTOK / 8, 256>>>(tmp, l2g + (size_t)l * 256,
                                         l2b + (size_t)l * 256);
    }

    head_kernel<<<NWIN / 8, 256>>>(hw, hb, out);
}